// round 16
// baseline (speedup 1.0000x reference)
#include <cuda_runtime.h>
#include <math.h>

#define BB 4
#define NQ 4096
#define NGPTS 4096
#define NUPTS 8192
#define KNN 6
#define EPS_CS 1e-8f

#define THREADS 256
#define TILE 512

// row-min scratch layout: [up 32768][off 32768][gt_vs_up 16384][gt_vs_off 16384]
#define KEY_UP 0
#define KEY_OFF 32768
#define KEY_GTUP 65536
#define KEY_GTOFF 81920
#define KEY_TOTAL 98304

// acc slots: 0 smooth, 1 nor, 2 nor_ori, 3 up_row, 4 up_col, 5 off_row, 6 off_col
// All __device__ globals are zero-initialized at load; sum_kernel resets state,
// so graph replays are deterministic.
__device__ double g_acc[7];
__device__ unsigned int g_done;
__device__ float g_nor_gt[BB * NQ * 3];
__device__ float g_ori_pro[BB * NQ * 3];
__device__ int g_knn[BB * NQ * KNN];
__device__ unsigned int g_min_key[KEY_TOTAL];   // holds ~fkey(e); 0 = identity for atomicMax

// ---- order-preserving float<->uint key ----
__device__ __forceinline__ unsigned int fkey(float f) {
    unsigned int u = __float_as_uint(f);
    return (u & 0x80000000u) ? ~u : (u | 0x80000000u);
}
__device__ __forceinline__ float funkey(unsigned int k) {
    unsigned int u = (k & 0x80000000u) ? (k & 0x7FFFFFFFu) : ~k;
    return __uint_as_float(u);
}

__device__ __forceinline__ void block_add(double v, int slot) {
    __shared__ double ws[8];
    int lane = threadIdx.x & 31;
    int w = threadIdx.x >> 5;
    int nw = blockDim.x >> 5;
#pragma unroll
    for (int o = 16; o > 0; o >>= 1)
        v += __shfl_down_sync(0xffffffffu, v, o);
    __syncthreads();
    if (lane == 0) ws[w] = v;
    __syncthreads();
    if (threadIdx.x == 0) {
        double t = 0.0;
        for (int i = 0; i < nw; i++) t += ws[i];
        atomicAdd(&g_acc[slot], t);
    }
    __syncthreads();
}

__device__ __forceinline__ unsigned long long pack2(float a, float b) {
    unsigned long long r;
    asm("mov.b64 %0, {%1, %2};" : "=l"(r) : "f"(a), "f"(b));
    return r;
}

__device__ __forceinline__ unsigned long long fma2_chain(
    unsigned long long xp, unsigned long long yp, unsigned long long zp,
    unsigned long long hp, unsigned long long mx, unsigned long long my,
    unsigned long long mz) {
    unsigned long long e;
    asm("fma.rn.f32x2 %0, %1, %2, %3;" : "=l"(e) : "l"(zp), "l"(mz), "l"(hp));
    asm("fma.rn.f32x2 %0, %1, %2, %0;" : "+l"(e) : "l"(yp), "l"(my));
    asm("fma.rn.f32x2 %0, %1, %2, %0;" : "+l"(e) : "l"(xp), "l"(mx));
    return e;
}
__device__ __forceinline__ void unpack2(unsigned long long e, float& lo, float& hi) {
    asm("mov.b64 {%0, %1}, %2;" : "=f"(lo), "=f"(hi) : "l"(e));
}

// fill pair-SoA tile: tAf[j]=(x0,x1,y0,y1) tBf[j]=(z0,z1,h0,h1), h=0.5*|c|^2
__device__ __forceinline__ void fill_tile(const float* __restrict__ cb, int cstride,
                                          int t0, float4* tAf, float4* tBf) {
    for (int j = threadIdx.x; j < TILE / 2; j += THREADS) {
        const float* c0 = cb + (size_t)(t0 + 2 * j) * cstride;
        const float* c1 = c0 + cstride;
        float x0 = c0[0], y0 = c0[1], z0 = c0[2];
        float x1 = c1[0], y1 = c1[1], z1 = c1[2];
        tAf[j] = make_float4(x0, x1, y0, y1);
        tBf[j] = make_float4(z0, z1,
                             0.5f * (x0 * x0 + y0 * y0 + z0 * z0),
                             0.5f * (x1 * x1 + y1 * y1 + z1 * z1));
    }
}

// 2 rows per thread, candidate range split into nparts chunks; packed pair evals.
// Partial row-min merged globally via atomicMax on inverted key (identity 0).
__device__ void chamfer2(const float* __restrict__ rows, int nrows_b, int rstride,
                         const float* __restrict__ cands, int ncand_b, int cstride,
                         int keybase, int rb, int part, int nparts, float4* tile4) {
    ulonglong2* tA = (ulonglong2*)tile4;
    ulonglong2* tB = (ulonglong2*)(tile4 + TILE / 2);
    float4* tAf = tile4;
    float4* tBf = tile4 + TILE / 2;

    int r0 = rb * (2 * THREADS) + threadIdx.x;   // 512-row chunk, never straddles a batch
    int r1 = r0 + THREADS;
    int b = r0 / nrows_b;
    const float* rp0 = rows + (size_t)r0 * rstride;
    const float* rp1 = rows + (size_t)r1 * rstride;
    float p0x = rp0[0], p0y = rp0[1], p0z = rp0[2];
    float p1x = rp1[0], p1y = rp1[1], p1z = rp1[2];
    unsigned long long m0x = pack2(-p0x, -p0x), m0y = pack2(-p0y, -p0y), m0z = pack2(-p0z, -p0z);
    unsigned long long m1x = pack2(-p1x, -p1x), m1y = pack2(-p1y, -p1y), m1z = pack2(-p1z, -p1z);
    float b00 = 3.4e38f, b01 = 3.4e38f, b10 = 3.4e38f, b11 = 3.4e38f;

    const int qc = ncand_b / nparts;
    const float* cb = cands + ((size_t)b * ncand_b + (size_t)part * qc) * cstride;
    for (int t0 = 0; t0 < qc; t0 += TILE) {
        __syncthreads();
        fill_tile(cb, cstride, t0, tAf, tBf);
        __syncthreads();
#pragma unroll 8
        for (int j = 0; j < TILE / 2; j++) {
            ulonglong2 A = tA[j];
            ulonglong2 B = tB[j];
            float lo, hi;
            unpack2(fma2_chain(A.x, A.y, B.x, B.y, m0x, m0y, m0z), lo, hi);
            b00 = fminf(b00, lo); b01 = fminf(b01, hi);
            unpack2(fma2_chain(A.x, A.y, B.x, B.y, m1x, m1y, m1z), lo, hi);
            b10 = fminf(b10, lo); b11 = fminf(b11, hi);
        }
    }
    atomicMax(&g_min_key[keybase + r0], ~fkey(fminf(b00, b01)));
    atomicMax(&g_min_key[keybase + r1], ~fkey(fminf(b10, b11)));
}

// NN pts->gt argmin + dependent per-point math (packed inner loop).
__device__ void task_nn(const float* __restrict__ ori_pre, const float* __restrict__ nor_pre,
                        const float* __restrict__ pts, const float* __restrict__ gt,
                        int rb, float4* tile4) {
    ulonglong2* tA = (ulonglong2*)tile4;
    ulonglong2* tB = (ulonglong2*)(tile4 + TILE / 2);
    float4* tAf = tile4;
    float4* tBf = tile4 + TILE / 2;

    int gidx = rb * THREADS + threadIdx.x;
    int b = gidx / NQ;
    const float* pp = pts + (size_t)gidx * 3;
    float px = pp[0], py = pp[1], pz = pp[2];
    unsigned long long mx = pack2(-px, -px), my = pack2(-py, -py), mz = pack2(-pz, -pz);
    float best = 3.4e38f;
    int bj = 0;
    const float* gb = gt + (size_t)b * NGPTS * 6;
    for (int t0 = 0; t0 < NGPTS; t0 += TILE) {
        __syncthreads();
        fill_tile(gb, 6, t0, tAf, tBf);
        __syncthreads();
#pragma unroll 4
        for (int j = 0; j < TILE / 2; j++) {
            ulonglong2 A = tA[j];
            ulonglong2 B = tB[j];
            float lo, hi;
            unpack2(fma2_chain(A.x, A.y, B.x, B.y, mx, my, mz), lo, hi);
            if (fminf(lo, hi) < best) {
                if (lo < best) { best = lo; bj = t0 + 2 * j; }
                if (hi < best) { best = hi; bj = t0 + 2 * j + 1; }
            }
        }
    }
    float nx = gb[(size_t)bj * 6 + 3];
    float ny = gb[(size_t)bj * 6 + 4];
    float nz = gb[(size_t)bj * 6 + 5];
    g_nor_gt[(size_t)gidx * 3 + 0] = nx;
    g_nor_gt[(size_t)gidx * 3 + 1] = ny;
    g_nor_gt[(size_t)gidx * 3 + 2] = nz;

    float ox = ori_pre[(size_t)gidx * 3 + 0];
    float oy = ori_pre[(size_t)gidx * 3 + 1];
    float oz = ori_pre[(size_t)gidx * 3 + 2];
    float on = sqrtf(ox * ox + oy * oy + oz * oz + 1e-8f);
    float oi = 1.0f / (on + 1e-10f);
    ox *= oi; oy *= oi; oz *= oi;

    float dn = nx * ox + ny * oy + nz * oz;
    float tx = ox - nx * dn, ty = oy - ny * dn, tz = oz - nz * dn;
    float tn = sqrtf(tx * tx + ty * ty + tz * tz + 1e-8f);
    float ti = 1.0f / (tn + 1e-10f);
    g_ori_pro[(size_t)gidx * 3 + 0] = tx * ti;
    g_ori_pro[(size_t)gidx * 3 + 1] = ty * ti;
    g_ori_pro[(size_t)gidx * 3 + 2] = tz * ti;

    float qx = nor_pre[(size_t)gidx * 3 + 0];
    float qy = nor_pre[(size_t)gidx * 3 + 1];
    float qz = nor_pre[(size_t)gidx * 3 + 2];
    float qn = sqrtf(qx * qx + qy * qy + qz * qz + 1e-8f);
    float qi = 1.0f / (qn + 1e-10f);
    qx *= qi; qy *= qi; qz *= qi;
    float na = fmaxf(sqrtf(nx * nx + ny * ny + nz * nz), EPS_CS);
    float nb = fmaxf(sqrtf(qx * qx + qy * qy + qz * qz), EPS_CS);
    float cs = (nx * qx + ny * qy + nz * qz) / (na * nb);

    block_add((double)(1.0f - fabsf(cs)), 1);
    block_add((double)fabsf(dn), 2);
}

// KNN pts->pts top-6 (stable ties), packed inner loop -> store indices.
__device__ void task_knn(const float* __restrict__ pts, int rb, float4* tile4) {
    ulonglong2* tA = (ulonglong2*)tile4;
    ulonglong2* tB = (ulonglong2*)(tile4 + TILE / 2);
    float4* tAf = tile4;
    float4* tBf = tile4 + TILE / 2;

    int gidx = rb * THREADS + threadIdx.x;
    int b = gidx / NQ;
    const float* pp = pts + (size_t)gidx * 3;
    float px = pp[0], py = pp[1], pz = pp[2];
    unsigned long long mx = pack2(-px, -px), my = pack2(-py, -py), mz = pack2(-pz, -pz);

    float bd[KNN];
    int bi[KNN];
#pragma unroll
    for (int k = 0; k < KNN; k++) { bd[k] = 3.4e38f; bi[k] = 0; }

    const float* cb = pts + (size_t)b * NQ * 3;
    for (int t0 = 0; t0 < NQ; t0 += TILE) {
        __syncthreads();
        fill_tile(cb, 3, t0, tAf, tBf);
        __syncthreads();
#pragma unroll 4
        for (int j = 0; j < TILE / 2; j++) {
            ulonglong2 A = tA[j];
            ulonglong2 B = tB[j];
            float lo, hi;
            unpack2(fma2_chain(A.x, A.y, B.x, B.y, mx, my, mz), lo, hi);
            if (fminf(lo, hi) < bd[KNN - 1]) {
                float nd = lo; int ni = t0 + 2 * j;
#pragma unroll
                for (int k = 0; k < KNN; k++) {
                    bool lt = nd < bd[k];
                    float td = bd[k]; int ti2 = bi[k];
                    if (lt) { bd[k] = nd; bi[k] = ni; nd = td; ni = ti2; }
                }
                nd = hi; ni = t0 + 2 * j + 1;
#pragma unroll
                for (int k = 0; k < KNN; k++) {
                    bool lt = nd < bd[k];
                    float td = bd[k]; int ti2 = bi[k];
                    if (lt) { bd[k] = nd; bi[k] = ni; nd = td; ni = ti2; }
                }
            }
        }
    }
#pragma unroll
    for (int k = 0; k < KNN; k++) g_knn[(size_t)gidx * KNN + k] = bi[k];
}

// Balanced grid of 256-thread blocks (8 warps each), ~1.05M evals/block:
//  gt-chamfer: 32 row-blocks (512 rows) x 4 candidate chunks (2048) = 128 blocks
//  up/off    : 64 row-blocks (512 rows) x 2 candidate chunks (2048) = 128 blocks
//  knn/nn    : 64 blocks each (256 rows x 4096 cands)
#define KNN_B 64
#define NN_B 64
#define GTUP_B 128
#define GTOFF_B 128
#define UP_B 128
#define OFF_B 128
#define HEAVY_BLOCKS (KNN_B + NN_B + GTUP_B + GTOFF_B + UP_B + OFF_B)  // 640

__global__ void __launch_bounds__(THREADS) heavy_kernel(
    const float* __restrict__ ori_pre, const float* __restrict__ nor_pre,
    const float* __restrict__ xyz_up, const float* __restrict__ xyz_offset,
    const float* __restrict__ pts, const float* __restrict__ gt) {
    __shared__ float4 tile4[TILE];
    int bid = blockIdx.x;
    if (bid < KNN_B) {
        task_knn(pts, bid, tile4);
    } else if (bid < KNN_B + NN_B) {
        task_nn(ori_pre, nor_pre, pts, gt, bid - KNN_B, tile4);
    } else if (bid < KNN_B + NN_B + GTUP_B) {
        int r = bid - (KNN_B + NN_B);
        chamfer2(gt, NGPTS, 6, xyz_up, NUPTS, 3, KEY_GTUP, r >> 2, r & 3, 4, tile4);
    } else if (bid < KNN_B + NN_B + GTUP_B + GTOFF_B) {
        int r = bid - (KNN_B + NN_B + GTUP_B);
        chamfer2(gt, NGPTS, 6, xyz_offset, NUPTS, 3, KEY_GTOFF, r >> 2, r & 3, 4, tile4);
    } else if (bid < KNN_B + NN_B + GTUP_B + GTOFF_B + UP_B) {
        int r = bid - (KNN_B + NN_B + GTUP_B + GTOFF_B);
        chamfer2(xyz_up, NUPTS, 3, gt, NGPTS, 6, KEY_UP, r >> 1, r & 1, 2, tile4);
    } else {
        int r = bid - (KNN_B + NN_B + GTUP_B + GTOFF_B + UP_B);
        chamfer2(xyz_offset, NUPTS, 3, gt, NGPTS, 6, KEY_OFF, r >> 1, r & 1, 2, tile4);
    }
}

// smooth loss from stored knn indices
#define SMOOTH_B (BB * NQ / THREADS)   // 64
__global__ void __launch_bounds__(THREADS) smooth_kernel() {
    int gidx = blockIdx.x * THREADS + threadIdx.x;
    int b = gidx / NQ;

    float box = g_ori_pro[(size_t)gidx * 3 + 0];
    float boy = g_ori_pro[(size_t)gidx * 3 + 1];
    float boz = g_ori_pro[(size_t)gidx * 3 + 2];
    float bnx = g_nor_gt[(size_t)gidx * 3 + 0];
    float bny = g_nor_gt[(size_t)gidx * 3 + 1];
    float bnz = g_nor_gt[(size_t)gidx * 3 + 2];
    float rx = boy * bnz - boz * bny;
    float ry = boz * bnx - box * bnz;
    float rz = box * bny - boy * bnx;
    float nbo = fmaxf(sqrtf(box * box + boy * boy + boz * boz), EPS_CS);
    float nbr = fmaxf(sqrtf(rx * rx + ry * ry + rz * rz), EPS_CS);

    double s = 0.0;
#pragma unroll
    for (int k = 0; k < KNN; k++) {
        size_t gi = (size_t)b * NQ + g_knn[(size_t)gidx * KNN + k];
        float gnx = g_nor_gt[gi * 3 + 0];
        float gny = g_nor_gt[gi * 3 + 1];
        float gnz = g_nor_gt[gi * 3 + 2];
        float gox = g_ori_pro[gi * 3 + 0];
        float goy = g_ori_pro[gi * 3 + 1];
        float goz = g_ori_pro[gi * 3 + 2];
        float ndot = gnx * bnx + gny * bny + gnz * bnz;
        float wraw = expf(-ndot / 0.3f) * 10.0f + 1.0f;
        float w = (wraw < 4.0f) ? 1.0f : 5.0f;
        float ng = fmaxf(sqrtf(gox * gox + goy * goy + goz * goz), EPS_CS);
        float cos0 = (gox * box + goy * boy + goz * boz) / (ng * nbo);
        float cos1 = (gox * rx + goy * ry + goz * rz) / (ng * nbr);
        float c = fminf(1.0f - fabsf(cos0), 1.0f - fabsf(cos1));
        s += (double)(w * c);
    }
    block_add(s, 0);
}

// sum per-row chamfer mins (d = |p|^2 + 2*e_min), reset keys, finalize.
#define SUM_B 96
__global__ void __launch_bounds__(THREADS) sum_kernel(
    const float* __restrict__ xyz_up, const float* __restrict__ xyz_offset,
    const float* __restrict__ gt, float* __restrict__ out) {
    double s3 = 0.0, s5 = 0.0, s4 = 0.0, s6 = 0.0;
    for (int i = blockIdx.x * THREADS + threadIdx.x; i < KEY_TOTAL; i += SUM_B * THREADS) {
        float e = funkey(~g_min_key[i]);
        g_min_key[i] = 0u;   // identity for next call's atomicMax
        const float* p;
        int which;
        if (i < KEY_OFF) { p = xyz_up + (size_t)i * 3; which = 0; }
        else if (i < KEY_GTUP) { p = xyz_offset + (size_t)(i - KEY_OFF) * 3; which = 1; }
        else if (i < KEY_GTOFF) { p = gt + (size_t)(i - KEY_GTUP) * 6; which = 2; }
        else { p = gt + (size_t)(i - KEY_GTOFF) * 6; which = 3; }
        float sp = p[0] * p[0] + p[1] * p[1] + p[2] * p[2];
        double d = (double)(sp + 2.0f * e);
        if (which == 0) s3 += d;
        else if (which == 1) s5 += d;
        else if (which == 2) s4 += d;
        else s6 += d;
    }
    block_add(s3, 3);
    block_add(s5, 5);
    block_add(s4, 4);
    block_add(s6, 6);

    __threadfence();
    __shared__ int is_last;
    if (threadIdx.x == 0) {
        unsigned int d = atomicAdd(&g_done, 1u);
        is_last = (d == (unsigned int)(SUM_B - 1)) ? 1 : 0;
    }
    __syncthreads();
    if (is_last && threadIdx.x == 0) {
        __threadfence();
        volatile double* va = g_acc;
        double smooth = va[0] / (double)(BB * NQ * KNN);
        double lnor = va[1] / (double)(BB * NQ);
        double lno = va[2] / (double)(BB * NQ);
        double l_up = va[3] / (double)(BB * NUPTS) + va[4] / (double)(BB * NGPTS);
        double l_off = va[5] / (double)(BB * NUPTS) + va[6] / (double)(BB * NGPTS);
        double cd = l_up + 0.4 * l_off;
        double loss = smooth + lnor + 0.1 * lno + 200.0 * cd;
        out[0] = (float)loss;
        out[1] = (float)smooth;
        out[2] = (float)lnor;
        out[3] = (float)l_off;
        out[4] = (float)lno;
        out[5] = (float)l_up;
        out[6] = (float)l_up;
#pragma unroll
        for (int i = 0; i < 7; i++) g_acc[i] = 0.0;
        g_done = 0u;
    }
}

extern "C" void kernel_launch(void* const* d_in, const int* in_sizes, int n_in,
                              void* d_out, int out_size) {
    const float* ori_pre    = (const float*)d_in[0];
    const float* nor_pre    = (const float*)d_in[1];
    const float* xyz_up     = (const float*)d_in[2];
    const float* xyz_offset = (const float*)d_in[3];
    const float* pts        = (const float*)d_in[4];
    const float* gt         = (const float*)d_in[5];
    float* out = (float*)d_out;

    static int carveout_set = 0;
    if (!carveout_set) {
        cudaFuncSetAttribute(heavy_kernel, cudaFuncAttributePreferredSharedMemoryCarveout, 100);
        carveout_set = 1;
    }

    heavy_kernel<<<HEAVY_BLOCKS, THREADS>>>(ori_pre, nor_pre, xyz_up, xyz_offset, pts, gt);
    smooth_kernel<<<SMOOTH_B, THREADS>>>();
    sum_kernel<<<SUM_B, THREADS>>>(xyz_up, xyz_offset, gt, out);
}

// round 17
// speedup vs baseline: 1.1217x; 1.1217x over previous
#include <cuda_runtime.h>
#include <math.h>

#define BB 4
#define NQ 4096
#define NGPTS 4096
#define NUPTS 8192
#define KNN 6
#define EPS_CS 1e-8f

#define THREADS 256
#define TILE 512
#define NPTS_TOT (BB * NQ)   // 16384

// row-min scratch layout: [up 32768][off 32768][gt_vs_up 16384][gt_vs_off 16384]
#define KEY_UP 0
#define KEY_OFF 32768
#define KEY_GTUP 65536
#define KEY_GTOFF 81920
#define KEY_TOTAL 98304

// acc slots: 0 smooth, 1 nor, 2 nor_ori, 3 up_row, 4 up_col, 5 off_row, 6 off_col
// All __device__ globals are zero-initialized at load; kernels restore state each
// call (mid resets g_nn_key, sum resets g_min_key, finalize resets g_acc/g_done),
// so graph replays are deterministic.
__device__ double g_acc[7];
__device__ unsigned int g_done;
__device__ float g_nor_gt[NPTS_TOT * 3];
__device__ float g_ori_pro[NPTS_TOT * 3];
__device__ unsigned long long g_nn_key[NPTS_TOT];          // ~((fkey(e)<<32)|idx); 0 = identity for atomicMax
__device__ unsigned long long g_knn_keys[2 * NPTS_TOT * KNN]; // per-half sorted top-6 (plain stores)
__device__ unsigned int g_min_key[KEY_TOTAL];              // ~fkey(e); 0 = identity for atomicMax

// ---- order-preserving float<->uint key ----
__device__ __forceinline__ unsigned int fkey(float f) {
    unsigned int u = __float_as_uint(f);
    return (u & 0x80000000u) ? ~u : (u | 0x80000000u);
}
__device__ __forceinline__ float funkey(unsigned int k) {
    unsigned int u = (k & 0x80000000u) ? (k & 0x7FFFFFFFu) : ~k;
    return __uint_as_float(u);
}

__device__ __forceinline__ void block_add(double v, int slot) {
    __shared__ double ws[8];
    int lane = threadIdx.x & 31;
    int w = threadIdx.x >> 5;
    int nw = blockDim.x >> 5;
#pragma unroll
    for (int o = 16; o > 0; o >>= 1)
        v += __shfl_down_sync(0xffffffffu, v, o);
    __syncthreads();
    if (lane == 0) ws[w] = v;
    __syncthreads();
    if (threadIdx.x == 0) {
        double t = 0.0;
        for (int i = 0; i < nw; i++) t += ws[i];
        atomicAdd(&g_acc[slot], t);
    }
    __syncthreads();
}

__device__ __forceinline__ unsigned long long pack2(float a, float b) {
    unsigned long long r;
    asm("mov.b64 %0, {%1, %2};" : "=l"(r) : "f"(a), "f"(b));
    return r;
}

__device__ __forceinline__ unsigned long long fma2_chain(
    unsigned long long xp, unsigned long long yp, unsigned long long zp,
    unsigned long long hp, unsigned long long mx, unsigned long long my,
    unsigned long long mz) {
    unsigned long long e;
    asm("fma.rn.f32x2 %0, %1, %2, %3;" : "=l"(e) : "l"(zp), "l"(mz), "l"(hp));
    asm("fma.rn.f32x2 %0, %1, %2, %0;" : "+l"(e) : "l"(yp), "l"(my));
    asm("fma.rn.f32x2 %0, %1, %2, %0;" : "+l"(e) : "l"(xp), "l"(mx));
    return e;
}
__device__ __forceinline__ void unpack2(unsigned long long e, float& lo, float& hi) {
    asm("mov.b64 {%0, %1}, %2;" : "=f"(lo), "=f"(hi) : "l"(e));
}

// fill pair-SoA tile: tAf[j]=(x0,x1,y0,y1) tBf[j]=(z0,z1,h0,h1), h=0.5*|c|^2
__device__ __forceinline__ void fill_tile(const float* __restrict__ cb, int cstride,
                                          int t0, float4* tAf, float4* tBf) {
    for (int j = threadIdx.x; j < TILE / 2; j += THREADS) {
        const float* c0 = cb + (size_t)(t0 + 2 * j) * cstride;
        const float* c1 = c0 + cstride;
        float x0 = c0[0], y0 = c0[1], z0 = c0[2];
        float x1 = c1[0], y1 = c1[1], z1 = c1[2];
        tAf[j] = make_float4(x0, x1, y0, y1);
        tBf[j] = make_float4(z0, z1,
                             0.5f * (x0 * x0 + y0 * y0 + z0 * z0),
                             0.5f * (x1 * x1 + y1 * y1 + z1 * z1));
    }
}

// 2 rows per thread, candidate range split into nparts chunks; packed pair evals.
__device__ void chamfer2(const float* __restrict__ rows, int nrows_b, int rstride,
                         const float* __restrict__ cands, int ncand_b, int cstride,
                         int keybase, int rb, int part, int nparts, float4* tile4) {
    ulonglong2* tA = (ulonglong2*)tile4;
    ulonglong2* tB = (ulonglong2*)(tile4 + TILE / 2);
    float4* tAf = tile4;
    float4* tBf = tile4 + TILE / 2;

    int r0 = rb * (2 * THREADS) + threadIdx.x;   // 512-row chunk, never straddles a batch
    int r1 = r0 + THREADS;
    int b = r0 / nrows_b;
    const float* rp0 = rows + (size_t)r0 * rstride;
    const float* rp1 = rows + (size_t)r1 * rstride;
    float p0x = rp0[0], p0y = rp0[1], p0z = rp0[2];
    float p1x = rp1[0], p1y = rp1[1], p1z = rp1[2];
    unsigned long long m0x = pack2(-p0x, -p0x), m0y = pack2(-p0y, -p0y), m0z = pack2(-p0z, -p0z);
    unsigned long long m1x = pack2(-p1x, -p1x), m1y = pack2(-p1y, -p1y), m1z = pack2(-p1z, -p1z);
    float b00 = 3.4e38f, b01 = 3.4e38f, b10 = 3.4e38f, b11 = 3.4e38f;

    const int qc = ncand_b / nparts;
    const float* cb = cands + ((size_t)b * ncand_b + (size_t)part * qc) * cstride;
    for (int t0 = 0; t0 < qc; t0 += TILE) {
        __syncthreads();
        fill_tile(cb, cstride, t0, tAf, tBf);
        __syncthreads();
#pragma unroll 8
        for (int j = 0; j < TILE / 2; j++) {
            ulonglong2 A = tA[j];
            ulonglong2 B = tB[j];
            float lo, hi;
            unpack2(fma2_chain(A.x, A.y, B.x, B.y, m0x, m0y, m0z), lo, hi);
            b00 = fminf(b00, lo); b01 = fminf(b01, hi);
            unpack2(fma2_chain(A.x, A.y, B.x, B.y, m1x, m1y, m1z), lo, hi);
            b10 = fminf(b10, lo); b11 = fminf(b11, hi);
        }
    }
    atomicMax(&g_min_key[keybase + r0], ~fkey(fminf(b00, b01)));
    atomicMax(&g_min_key[keybase + r1], ~fkey(fminf(b10, b11)));
}

// NN pts->gt argmin scan over a candidate half; 2 rows per thread.
// Publishes packed (fkey(e)<<32 | idx) via atomicMax on complement (identity 0).
__device__ void task_nn_scan(const float* __restrict__ pts, const float* __restrict__ gt,
                             int rb, int half, float4* tile4) {
    ulonglong2* tA = (ulonglong2*)tile4;
    ulonglong2* tB = (ulonglong2*)(tile4 + TILE / 2);
    float4* tAf = tile4;
    float4* tBf = tile4 + TILE / 2;

    int r0 = rb * (2 * THREADS) + threadIdx.x;
    int r1 = r0 + THREADS;
    int b = r0 / NQ;
    const float* pp0 = pts + (size_t)r0 * 3;
    const float* pp1 = pts + (size_t)r1 * 3;
    unsigned long long m0x = pack2(-pp0[0], -pp0[0]), m0y = pack2(-pp0[1], -pp0[1]),
                       m0z = pack2(-pp0[2], -pp0[2]);
    unsigned long long m1x = pack2(-pp1[0], -pp1[0]), m1y = pack2(-pp1[1], -pp1[1]),
                       m1z = pack2(-pp1[2], -pp1[2]);
    float b0 = 3.4e38f, b1 = 3.4e38f;
    int j0 = 0, j1 = 0;

    const int hc = NGPTS / 2;
    const float* gb = gt + ((size_t)b * NGPTS + (size_t)half * hc) * 6;
    for (int t0 = 0; t0 < hc; t0 += TILE) {
        __syncthreads();
        fill_tile(gb, 6, t0, tAf, tBf);
        __syncthreads();
#pragma unroll 4
        for (int j = 0; j < TILE / 2; j++) {
            ulonglong2 A = tA[j];
            ulonglong2 B = tB[j];
            float lo, hi;
            unpack2(fma2_chain(A.x, A.y, B.x, B.y, m0x, m0y, m0z), lo, hi);
            if (fminf(lo, hi) < b0) {
                if (lo < b0) { b0 = lo; j0 = t0 + 2 * j; }
                if (hi < b0) { b0 = hi; j0 = t0 + 2 * j + 1; }
            }
            unpack2(fma2_chain(A.x, A.y, B.x, B.y, m1x, m1y, m1z), lo, hi);
            if (fminf(lo, hi) < b1) {
                if (lo < b1) { b1 = lo; j1 = t0 + 2 * j; }
                if (hi < b1) { b1 = hi; j1 = t0 + 2 * j + 1; }
            }
        }
    }
    unsigned long long k0 = ((unsigned long long)fkey(b0) << 32) | (unsigned int)(half * hc + j0);
    unsigned long long k1 = ((unsigned long long)fkey(b1) << 32) | (unsigned int)(half * hc + j1);
    atomicMax(&g_nn_key[r0], ~k0);
    atomicMax(&g_nn_key[r1], ~k1);
}

// KNN pts->pts top-6 over a candidate half (stable ties) -> store sorted keys.
__device__ void task_knn_scan(const float* __restrict__ pts, int rb, int half, float4* tile4) {
    ulonglong2* tA = (ulonglong2*)tile4;
    ulonglong2* tB = (ulonglong2*)(tile4 + TILE / 2);
    float4* tAf = tile4;
    float4* tBf = tile4 + TILE / 2;

    int gidx = rb * THREADS + threadIdx.x;   // 256 rows/block
    int b = gidx / NQ;
    const float* pp = pts + (size_t)gidx * 3;
    unsigned long long mx = pack2(-pp[0], -pp[0]), my = pack2(-pp[1], -pp[1]),
                       mz = pack2(-pp[2], -pp[2]);

    float bd[KNN];
    int bi[KNN];
#pragma unroll
    for (int k = 0; k < KNN; k++) { bd[k] = 3.4e38f; bi[k] = 0; }

    const int hc = NQ / 2;
    const float* cb = pts + ((size_t)b * NQ + (size_t)half * hc) * 3;
    for (int t0 = 0; t0 < hc; t0 += TILE) {
        __syncthreads();
        fill_tile(cb, 3, t0, tAf, tBf);
        __syncthreads();
#pragma unroll 4
        for (int j = 0; j < TILE / 2; j++) {
            ulonglong2 A = tA[j];
            ulonglong2 B = tB[j];
            float lo, hi;
            unpack2(fma2_chain(A.x, A.y, B.x, B.y, mx, my, mz), lo, hi);
            if (fminf(lo, hi) < bd[KNN - 1]) {
                float nd = lo; int ni = t0 + 2 * j;
#pragma unroll
                for (int k = 0; k < KNN; k++) {
                    bool lt = nd < bd[k];
                    float td = bd[k]; int ti2 = bi[k];
                    if (lt) { bd[k] = nd; bi[k] = ni; nd = td; ni = ti2; }
                }
                nd = hi; ni = t0 + 2 * j + 1;
#pragma unroll
                for (int k = 0; k < KNN; k++) {
                    bool lt = nd < bd[k];
                    float td = bd[k]; int ti2 = bi[k];
                    if (lt) { bd[k] = nd; bi[k] = ni; nd = td; ni = ti2; }
                }
            }
        }
    }
    unsigned long long* dst = &g_knn_keys[((size_t)half * NPTS_TOT + gidx) * KNN];
#pragma unroll
    for (int k = 0; k < KNN; k++)
        dst[k] = ((unsigned long long)fkey(bd[k]) << 32) | (unsigned int)(half * hc + bi[k]);
}

// Block layout: 704 blocks of 256 threads.
#define NN_B 64      // 32 row-blocks (512 rows) x 2 halves (2048 cands)
#define KNN_B 128    // 64 row-blocks (256 rows) x 2 halves (2048 cands)
#define GTUP_B 128   // 32 row-blocks (512 rows) x 4 chunks (2048 cands)
#define GTOFF_B 128
#define UP_B 128     // 64 row-blocks (512 rows) x 2 chunks (2048 cands)
#define OFF_B 128
#define HEAVY_BLOCKS (NN_B + KNN_B + GTUP_B + GTOFF_B + UP_B + OFF_B)  // 704

__global__ void __launch_bounds__(THREADS) heavy_kernel(
    const float* __restrict__ ori_pre, const float* __restrict__ nor_pre,
    const float* __restrict__ xyz_up, const float* __restrict__ xyz_offset,
    const float* __restrict__ pts, const float* __restrict__ gt) {
    __shared__ float4 tile4[TILE];
    int bid = blockIdx.x;
    if (bid < NN_B) {
        task_nn_scan(pts, gt, bid >> 1, bid & 1, tile4);
    } else if (bid < NN_B + KNN_B) {
        int r = bid - NN_B;
        task_knn_scan(pts, r >> 1, r & 1, tile4);
    } else if (bid < NN_B + KNN_B + GTUP_B) {
        int r = bid - (NN_B + KNN_B);
        chamfer2(gt, NGPTS, 6, xyz_up, NUPTS, 3, KEY_GTUP, r >> 2, r & 3, 4, tile4);
    } else if (bid < NN_B + KNN_B + GTUP_B + GTOFF_B) {
        int r = bid - (NN_B + KNN_B + GTUP_B);
        chamfer2(gt, NGPTS, 6, xyz_offset, NUPTS, 3, KEY_GTOFF, r >> 2, r & 3, 4, tile4);
    } else if (bid < NN_B + KNN_B + GTUP_B + GTOFF_B + UP_B) {
        int r = bid - (NN_B + KNN_B + GTUP_B + GTOFF_B);
        chamfer2(xyz_up, NUPTS, 3, gt, NGPTS, 6, KEY_UP, r >> 1, r & 1, 2, tile4);
    } else {
        int r = bid - (NN_B + KNN_B + GTUP_B + GTOFF_B + UP_B);
        chamfer2(xyz_offset, NUPTS, 3, gt, NGPTS, 6, KEY_OFF, r >> 1, r & 1, 2, tile4);
    }
}

// Resolve NN argmin -> per-point epilogue (nor_gt, ori_pro, loss_nor, loss_nor_ori).
#define MID_B (NPTS_TOT / THREADS)   // 64
__global__ void __launch_bounds__(THREADS) mid_kernel(
    const float* __restrict__ ori_pre, const float* __restrict__ nor_pre,
    const float* __restrict__ gt) {
    int gidx = blockIdx.x * THREADS + threadIdx.x;
    int b = gidx / NQ;
    unsigned long long key = ~g_nn_key[gidx];
    g_nn_key[gidx] = 0ull;   // identity for next replay
    int bj = (int)(unsigned int)(key & 0xFFFFFFFFull);
    const float* gb = gt + (size_t)b * NGPTS * 6;

    float nx = gb[(size_t)bj * 6 + 3];
    float ny = gb[(size_t)bj * 6 + 4];
    float nz = gb[(size_t)bj * 6 + 5];
    g_nor_gt[(size_t)gidx * 3 + 0] = nx;
    g_nor_gt[(size_t)gidx * 3 + 1] = ny;
    g_nor_gt[(size_t)gidx * 3 + 2] = nz;

    float ox = ori_pre[(size_t)gidx * 3 + 0];
    float oy = ori_pre[(size_t)gidx * 3 + 1];
    float oz = ori_pre[(size_t)gidx * 3 + 2];
    float on = sqrtf(ox * ox + oy * oy + oz * oz + 1e-8f);
    float oi = 1.0f / (on + 1e-10f);
    ox *= oi; oy *= oi; oz *= oi;

    float dn = nx * ox + ny * oy + nz * oz;
    float tx = ox - nx * dn, ty = oy - ny * dn, tz = oz - nz * dn;
    float tn = sqrtf(tx * tx + ty * ty + tz * tz + 1e-8f);
    float ti = 1.0f / (tn + 1e-10f);
    g_ori_pro[(size_t)gidx * 3 + 0] = tx * ti;
    g_ori_pro[(size_t)gidx * 3 + 1] = ty * ti;
    g_ori_pro[(size_t)gidx * 3 + 2] = tz * ti;

    float qx = nor_pre[(size_t)gidx * 3 + 0];
    float qy = nor_pre[(size_t)gidx * 3 + 1];
    float qz = nor_pre[(size_t)gidx * 3 + 2];
    float qn = sqrtf(qx * qx + qy * qy + qz * qz + 1e-8f);
    float qi = 1.0f / (qn + 1e-10f);
    qx *= qi; qy *= qi; qz *= qi;
    float na = fmaxf(sqrtf(nx * nx + ny * ny + nz * nz), EPS_CS);
    float nb = fmaxf(sqrtf(qx * qx + qy * qy + qz * qz), EPS_CS);
    float cs = (nx * qx + ny * qy + nz * qz) / (na * nb);

    block_add((double)(1.0f - fabsf(cs)), 1);
    block_add((double)fabsf(dn), 2);
}

// Tail: smooth (merged knn halves) + chamfer sums + finalize.
#define SMOOTH_B (NPTS_TOT / THREADS)  // 64
#define SUM_B 96
#define TAIL_B (SMOOTH_B + SUM_B)      // 160

__device__ void do_smooth(int rb) {
    int gidx = rb * THREADS + threadIdx.x;
    int b = gidx / NQ;

    float box = g_ori_pro[(size_t)gidx * 3 + 0];
    float boy = g_ori_pro[(size_t)gidx * 3 + 1];
    float boz = g_ori_pro[(size_t)gidx * 3 + 2];
    float bnx = g_nor_gt[(size_t)gidx * 3 + 0];
    float bny = g_nor_gt[(size_t)gidx * 3 + 1];
    float bnz = g_nor_gt[(size_t)gidx * 3 + 2];
    float rx = boy * bnz - boz * bny;
    float ry = boz * bnx - box * bnz;
    float rz = box * bny - boy * bnx;
    float nbo = fmaxf(sqrtf(box * box + boy * boy + boz * boz), EPS_CS);
    float nbr = fmaxf(sqrtf(rx * rx + ry * ry + rz * rz), EPS_CS);

    const unsigned long long* la = &g_knn_keys[(size_t)gidx * KNN];
    const unsigned long long* lb = &g_knn_keys[((size_t)NPTS_TOT + gidx) * KNN];
    int ia = 0, ib = 0;

    double s = 0.0;
#pragma unroll
    for (int k = 0; k < KNN; k++) {
        unsigned long long ka = la[ia], kb = lb[ib];
        unsigned long long sel;
        if (ka <= kb) { sel = ka; ia++; } else { sel = kb; ib++; }
        int idx = (int)(unsigned int)(sel & 0xFFFFFFFFull);
        size_t gi = (size_t)b * NQ + idx;
        float gnx = g_nor_gt[gi * 3 + 0];
        float gny = g_nor_gt[gi * 3 + 1];
        float gnz = g_nor_gt[gi * 3 + 2];
        float gox = g_ori_pro[gi * 3 + 0];
        float goy = g_ori_pro[gi * 3 + 1];
        float goz = g_ori_pro[gi * 3 + 2];
        float ndot = gnx * bnx + gny * bny + gnz * bnz;
        float wraw = expf(-ndot / 0.3f) * 10.0f + 1.0f;
        float w = (wraw < 4.0f) ? 1.0f : 5.0f;
        float ng = fmaxf(sqrtf(gox * gox + goy * goy + goz * goz), EPS_CS);
        float cos0 = (gox * box + goy * boy + goz * boz) / (ng * nbo);
        float cos1 = (gox * rx + goy * ry + goz * rz) / (ng * nbr);
        float c = fminf(1.0f - fabsf(cos0), 1.0f - fabsf(cos1));
        s += (double)(w * c);
    }
    block_add(s, 0);
}

__device__ void do_sums(int rb, const float* __restrict__ xyz_up,
                        const float* __restrict__ xyz_offset,
                        const float* __restrict__ gt) {
    double s3 = 0.0, s5 = 0.0, s4 = 0.0, s6 = 0.0;
    for (int i = rb * THREADS + threadIdx.x; i < KEY_TOTAL; i += SUM_B * THREADS) {
        float e = funkey(~g_min_key[i]);
        g_min_key[i] = 0u;   // identity for next replay
        const float* p;
        int which;
        if (i < KEY_OFF) { p = xyz_up + (size_t)i * 3; which = 0; }
        else if (i < KEY_GTUP) { p = xyz_offset + (size_t)(i - KEY_OFF) * 3; which = 1; }
        else if (i < KEY_GTOFF) { p = gt + (size_t)(i - KEY_GTUP) * 6; which = 2; }
        else { p = gt + (size_t)(i - KEY_GTOFF) * 6; which = 3; }
        float sp = p[0] * p[0] + p[1] * p[1] + p[2] * p[2];
        double d = (double)(sp + 2.0f * e);
        if (which == 0) s3 += d;
        else if (which == 1) s5 += d;
        else if (which == 2) s4 += d;
        else s6 += d;
    }
    block_add(s3, 3);
    block_add(s5, 5);
    block_add(s4, 4);
    block_add(s6, 6);
}

__global__ void __launch_bounds__(THREADS) tail_kernel(
    const float* __restrict__ xyz_up, const float* __restrict__ xyz_offset,
    const float* __restrict__ gt, float* __restrict__ out) {
    if (blockIdx.x < SMOOTH_B) {
        do_smooth(blockIdx.x);
    } else {
        do_sums(blockIdx.x - SMOOTH_B, xyz_up, xyz_offset, gt);
    }

    __threadfence();
    __shared__ int is_last;
    if (threadIdx.x == 0) {
        unsigned int d = atomicAdd(&g_done, 1u);
        is_last = (d == (unsigned int)(TAIL_B - 1)) ? 1 : 0;
    }
    __syncthreads();
    if (is_last && threadIdx.x == 0) {
        __threadfence();
        volatile double* va = g_acc;
        double smooth = va[0] / (double)(BB * NQ * KNN);
        double lnor = va[1] / (double)(BB * NQ);
        double lno = va[2] / (double)(BB * NQ);
        double l_up = va[3] / (double)(BB * NUPTS) + va[4] / (double)(BB * NGPTS);
        double l_off = va[5] / (double)(BB * NUPTS) + va[6] / (double)(BB * NGPTS);
        double cd = l_up + 0.4 * l_off;
        double loss = smooth + lnor + 0.1 * lno + 200.0 * cd;
        out[0] = (float)loss;
        out[1] = (float)smooth;
        out[2] = (float)lnor;
        out[3] = (float)l_off;
        out[4] = (float)lno;
        out[5] = (float)l_up;
        out[6] = (float)l_up;
#pragma unroll
        for (int i = 0; i < 7; i++) g_acc[i] = 0.0;
        g_done = 0u;
    }
}

extern "C" void kernel_launch(void* const* d_in, const int* in_sizes, int n_in,
                              void* d_out, int out_size) {
    const float* ori_pre    = (const float*)d_in[0];
    const float* nor_pre    = (const float*)d_in[1];
    const float* xyz_up     = (const float*)d_in[2];
    const float* xyz_offset = (const float*)d_in[3];
    const float* pts        = (const float*)d_in[4];
    const float* gt         = (const float*)d_in[5];
    float* out = (float*)d_out;

    static int carveout_set = 0;
    if (!carveout_set) {
        cudaFuncSetAttribute(heavy_kernel, cudaFuncAttributePreferredSharedMemoryCarveout, 100);
        carveout_set = 1;
    }

    heavy_kernel<<<HEAVY_BLOCKS, THREADS>>>(ori_pre, nor_pre, xyz_up, xyz_offset, pts, gt);
    mid_kernel<<<MID_B, THREADS>>>(ori_pre, nor_pre, gt);
    tail_kernel<<<TAIL_B, THREADS>>>(xyz_up, xyz_offset, gt, out);
}